// round 1
// baseline (speedup 1.0000x reference)
#include <cuda_runtime.h>

#define DD 512
#define BB 128
#define EPSF 1e-5f
#define LOG2E_F 1.4426950408889634f

// scratch (static device memory — no allocations)
__device__ float g_wk[3 * BB * DD];
__device__ float g_wq[3 * BB * DD];
__device__ float g_y [3 * BB * DD];

struct Ptr3 { const float* p[3]; };

__device__ __forceinline__ float ex2f(float x) {
    float y;
    asm("ex2.approx.ftz.f32 %0, %1;" : "=f"(y) : "f"(x));
    return y;
}

// ---- block reductions over 512 threads (16 warps) ----
__device__ __forceinline__ float blockReduceSum(float v, float* red) {
    int tid = threadIdx.x, lane = tid & 31, wid = tid >> 5;
    #pragma unroll
    for (int o = 16; o > 0; o >>= 1) v += __shfl_down_sync(0xffffffffu, v, o);
    if (lane == 0) red[wid] = v;
    __syncthreads();
    if (wid == 0) {
        float x = (lane < 16) ? red[lane] : 0.0f;
        #pragma unroll
        for (int o = 8; o > 0; o >>= 1) x += __shfl_down_sync(0xffffffffu, x, o);
        if (lane == 0) red[0] = x;
    }
    __syncthreads();
    float r = red[0];
    __syncthreads();
    return r;
}

__device__ __forceinline__ float blockReduceMax(float v, float* red) {
    int tid = threadIdx.x, lane = tid & 31, wid = tid >> 5;
    #pragma unroll
    for (int o = 16; o > 0; o >>= 1) v = fmaxf(v, __shfl_down_sync(0xffffffffu, v, o));
    if (lane == 0) red[wid] = v;
    __syncthreads();
    if (wid == 0) {
        float x = (lane < 16) ? red[lane] : -3.4e38f;
        #pragma unroll
        for (int o = 8; o > 0; o >>= 1) x = fmaxf(x, __shfl_down_sync(0xffffffffu, x, o));
        if (lane == 0) red[0] = x;
    }
    __syncthreads();
    float r = red[0];
    __syncthreads();
    return r;
}

__device__ __forceinline__ float blockReduceMin(float v, float* red) {
    int tid = threadIdx.x, lane = tid & 31, wid = tid >> 5;
    #pragma unroll
    for (int o = 16; o > 0; o >>= 1) v = fminf(v, __shfl_down_sync(0xffffffffu, v, o));
    if (lane == 0) red[wid] = v;
    __syncthreads();
    if (wid == 0) {
        float x = (lane < 16) ? red[lane] : 3.4e38f;
        #pragma unroll
        for (int o = 8; o > 0; o >>= 1) x = fminf(x, __shfl_down_sync(0xffffffffu, x, o));
        if (lane == 0) red[0] = x;
    }
    __syncthreads();
    float r = red[0];
    __syncthreads();
    return r;
}

// ---- grouped GEMV:  out[row, m] = sum_d src[row, d] * W[m, d] + bias[m] (+ residual) ----
// grid: (BB/GROUP, 3); block: 512 threads (one per output column m)
// mode 0 -> out = g_wk ; mode 1 -> out = g_wq ; mode 2 -> out = extout, add residual src
template <int GROUP>
__global__ void __launch_bounds__(512)
k_gemm(Ptr3 src, const float* __restrict__ W, const float* __restrict__ bias,
       float* extout, int mode)
{
    __shared__ __align__(16) float sm[GROUP * DD];
    int c   = blockIdx.y;
    int bg  = blockIdx.x;
    int tid = threadIdx.x;

    const float* s = src.p[c];
    #pragma unroll
    for (int r = 0; r < GROUP; r++)
        sm[r * DD + tid] = s[(bg * GROUP + r) * DD + tid];
    __syncthreads();

    const float4* wrow = reinterpret_cast<const float4*>(W + (size_t)tid * DD);
    float acc[GROUP];
    #pragma unroll
    for (int r = 0; r < GROUP; r++) acc[r] = 0.0f;

    #pragma unroll 2
    for (int d4 = 0; d4 < DD / 4; d4++) {
        float4 w4 = wrow[d4];
        #pragma unroll
        for (int r = 0; r < GROUP; r++) {
            float4 s4 = reinterpret_cast<const float4*>(sm + r * DD)[d4];  // broadcast
            acc[r] += s4.x * w4.x + s4.y * w4.y + s4.z * w4.z + s4.w * w4.w;
        }
    }

    float bv = bias[tid];
    float* out = (mode == 0) ? g_wk : (mode == 1) ? g_wq : extout;
    #pragma unroll
    for (int r = 0; r < GROUP; r++) {
        int row = c * BB + bg * GROUP + r;
        float o = acc[r] + bv;
        if (mode == 2) o += sm[r * DD + tid];  // residual: + y
        out[(size_t)row * DD + tid] = o;
    }
}

// ---- main fused kernel: one block per (batch, channel) ----
__global__ void __launch_bounds__(512)
k_main(Ptr3 x, Ptr3 h, Ptr3 kq,
       const float* __restrict__ kn_g, const float* __restrict__ kn_b,
       const float* __restrict__ norm_g, const float* __restrict__ norm_b)
{
    __shared__ float s_s[DD], s_u2[DD], s_m2[DD], s_coef[DD];
    __shared__ float red[32];

    int b = blockIdx.x, c = blockIdx.y, tid = threadIdx.x;
    int row = c * BB + b;

    float wk = g_wk[(size_t)row * DD + tid];
    float wq = g_wq[(size_t)row * DD + tid];
    float kv = h.p[c][(size_t)b * DD + tid];
    float qv = kq.p[c][(size_t)b * DD + tid];
    float vv = x.p[c][(size_t)b * DD + tid];

    const float inv_d = 1.0f / (float)DD;
    float mu_wk  = blockReduceSum(wk, red) * inv_d;
    float dk     = wk - mu_wk;
    float var_wk = blockReduceSum(dk * dk, red) * inv_d;
    float mu_wq  = blockReduceSum(wq, red) * inv_d;
    float dq     = wq - mu_wq;
    float var_wq = blockReduceSum(dq * dq, red) * inv_d;

    float g  = kn_g[tid];
    float cb = kn_b[tid];

    // rank-1 LN factorization
    float si = kv * rsqrtf(kv * kv * var_wk + EPSF);
    float ti = qv * rsqrtf(qv * qv * var_wq + EPSF);
    float Ai = dk * g;
    float Bi = dq * g;

    float P    = blockReduceSum(Ai * ti, red);
    float Qs   = blockReduceSum(Ai, red);
    float smax = blockReduceMax(si, red);
    float smin = blockReduceMin(si, red);

    // scores[i,j] = s_i * u_j + (j-only terms that cancel in softmax over i)
    float u2 = (P * Bi + Qs * cb) * LOG2E_F;          // log2-space
    float m2 = fmaxf(u2 * smax, u2 * smin);           // max_i of s_i*u_j (log2)
    s_s[tid]  = si;
    s_u2[tid] = u2;
    s_m2[tid] = m2;
    __syncthreads();

    // Pass A: Z_j = sum_i exp2(s_i*u2_j - m2_j)   (thread = column j)
    float z = 0.0f;
    #pragma unroll 8
    for (int i = 0; i < DD; i++)
        z += ex2f(fmaf(s_s[i], u2, -m2));
    s_coef[tid] = vv / z;
    __syncthreads();

    // Pass B: mha_i = sum_j coef_j * exp2(s_i*u2_j - m2_j)   (thread = row i)
    float acc = 0.0f;
    #pragma unroll 8
    for (int j = 0; j < DD; j++)
        acc += s_coef[j] * ex2f(fmaf(si, s_u2[j], -s_m2[j]));

    // residual + LayerNorm
    float y     = acc + vv;
    float mu_y  = blockReduceSum(y, red) * inv_d;
    float dy    = y - mu_y;
    float var_y = blockReduceSum(dy * dy, red) * inv_d;
    float yn    = dy * rsqrtf(var_y + EPSF) * norm_g[tid] + norm_b[tid];

    g_y[(size_t)row * DD + tid] = yn;
}

extern "C" void kernel_launch(void* const* d_in, const int* in_sizes, int n_in,
                              void* d_out, int out_size)
{
    (void)in_sizes; (void)n_in; (void)out_size;
    const float* r    = (const float*)d_in[0];
    const float* g    = (const float*)d_in[1];
    const float* b    = (const float*)d_in[2];
    const float* h_r  = (const float*)d_in[3];
    const float* h_g  = (const float*)d_in[4];
    const float* h_b  = (const float*)d_in[5];
    const float* k_r  = (const float*)d_in[6];
    const float* k_g  = (const float*)d_in[7];
    const float* k_b  = (const float*)d_in[8];
    const float* Wk   = (const float*)d_in[9];
    const float* bk   = (const float*)d_in[10];
    const float* Wq   = (const float*)d_in[11];
    const float* bq   = (const float*)d_in[12];
    const float* kn_g = (const float*)d_in[13];
    const float* kn_b = (const float*)d_in[14];
    const float* norm_g = (const float*)d_in[15];
    const float* norm_b = (const float*)d_in[16];
    const float* fc_w = (const float*)d_in[17];
    const float* fc_b = (const float*)d_in[18];
    float* out = (float*)d_out;

    Ptr3 X  = {{ r,   g,   b   }};
    Ptr3 H  = {{ h_r, h_g, h_b }};
    Ptr3 KQ = {{ k_r, k_g, k_b }};
    Ptr3 Ynull = {{ nullptr, nullptr, nullptr }};  // replaced below for fc

    dim3 blk(512);

    // Stage 1: w_k = h @ Wk.T + bk ; w_q = kidx @ Wq.T + bq
    k_gemm<16><<<dim3(BB / 16, 3), blk>>>(H,  Wk, bk, nullptr, 0);
    k_gemm<16><<<dim3(BB / 16, 3), blk>>>(KQ, Wq, bq, nullptr, 1);

    // Stage 2: collapsed attention + residual + LN -> g_y
    k_main<<<dim3(BB, 3), blk>>>(X, H, KQ, kn_g, kn_b, norm_g, norm_b);

    // Stage 3: out = y @ fc_w.T + fc_b + y   (src = g_y, read back inside kernel)
    // g_y is a device symbol; build Ptr3 from its device address via a tiny launch-free trick:
    // the kernel dereferences src.p[c]; we pass offsets into g_y through a helper kernel instead.
    // Simplest: use a dedicated launch where src points at g_y via cudaGetSymbolAddress-free path:
    // we can't take &g_y on host, so use a small kernel arg mode that reads g_y internally.
    // -> handled by passing mode==2 and a Ptr3 we fill from a device-side constant is not possible;
    //    instead reuse k_gemm with a device-side source selector: mode 2 ignores src only if null.
    // We instead launch a variant below.
    {
        // Fill Ptr3 with the device addresses of g_y using cudaGetSymbolAddress (host API,
        // enqueues nothing on the stream; safe under graph capture).
        static float* y_dev = nullptr;
        if (y_dev == nullptr) {
            void* p = nullptr;
            cudaGetSymbolAddress(&p, g_y);
            y_dev = (float*)p;
        }
        Ptr3 Y = {{ y_dev, y_dev + BB * DD, y_dev + 2 * BB * DD }};
        (void)Ynull;
        k_gemm<8><<<dim3(BB / 8, 3), blk>>>(Y, fc_w, fc_b, out, 2);
    }
}

// round 2
// speedup vs baseline: 2.0016x; 2.0016x over previous
#include <cuda_runtime.h>

#define DD 512
#define BB 128
#define EPSF 1e-5f
#define LOG2E_F 1.4426950408889634f

// scratch (static device memory — no allocations)
__device__ float g_wk[3 * BB * DD];
__device__ float g_wq[3 * BB * DD];
__device__ float g_y [3 * BB * DD];
__device__ float g_wt[3 * DD * DD];   // transposed Wk, Wq, fc_w

struct Ptr3 { const float* p[3]; };

__device__ __forceinline__ float ex2f(float x) {
    float y;
    asm("ex2.approx.ftz.f32 %0, %1;" : "=f"(y) : "f"(x));
    return y;
}

// ===================== transpose: g_wt[z][d][m] = W_z[m][d] =====================
__global__ void __launch_bounds__(256)
k_transpose(const float* __restrict__ W0, const float* __restrict__ W1,
            const float* __restrict__ W2)
{
    __shared__ float t[32][33];
    const float* W = (blockIdx.z == 0) ? W0 : (blockIdx.z == 1) ? W1 : W2;
    float* O = g_wt + (size_t)blockIdx.z * DD * DD;
    int x  = blockIdx.x * 32 + threadIdx.x;
    int y0 = blockIdx.y * 32;
    #pragma unroll
    for (int i = threadIdx.y; i < 32; i += 8)
        t[i][threadIdx.x] = W[(size_t)(y0 + i) * DD + x];
    __syncthreads();
    int xo  = blockIdx.y * 32 + threadIdx.x;
    int yo0 = blockIdx.x * 32;
    #pragma unroll
    for (int i = threadIdx.y; i < 32; i += 8)
        O[(size_t)(yo0 + i) * DD + xo] = t[threadIdx.x][i];
}

// ===================== register-tiled GEMM =====================
// out[row, m] = sum_d src[row, d] * Wt[d, m] + bias[m] (+ residual src)
// grid: (384/R row tiles, 4 col chunks of 128, Z matrices); block 256 threads.
// thread: col4 = tid&31 (4 consecutive cols), dq = tid>>5 (one of 8 d-chunks of 64).
struct GemmArgs {
    Ptr3 src[2];
    const float* bias[2];
    float* out[2];
    int wtsel[2];
};

template <int R, bool RES>
__global__ void __launch_bounds__(256)
k_gemm2(GemmArgs ga)
{
    extern __shared__ float smem[];
    float*  sm_src = smem;                       // R * DD floats
    float4* sm_red = (float4*)(smem + R * DD);   // 8 * R * 32 float4

    int z  = blockIdx.z;
    int t  = blockIdx.x;
    int cc = blockIdx.y;
    int tid = threadIdx.x;

    int c  = (t * R) / BB;
    int b0 = (t * R) % BB;
    const float* s  = ga.src[z].p[c] + (size_t)b0 * DD;
    const float* Wt = g_wt + (size_t)ga.wtsel[z] * DD * DD + cc * 128;

    // stage src rows into smem (coalesced)
    #pragma unroll 4
    for (int i = tid; i < R * DD / 4; i += 256)
        ((float4*)sm_src)[i] = ((const float4*)s)[i];
    __syncthreads();

    int col4 = tid & 31;
    int dq   = tid >> 5;          // warp-uniform
    const float4* wp = (const float4*)(Wt + (size_t)dq * 64 * DD) + col4;
    const float*  sb = sm_src + dq * 64;

    float4 acc[R];
    #pragma unroll
    for (int r = 0; r < R; r++) acc[r] = make_float4(0.f, 0.f, 0.f, 0.f);

    #pragma unroll 4
    for (int dd = 0; dd < 64; dd += 4) {
        float4 w0 = wp[(dd + 0) * (DD / 4)];
        float4 w1 = wp[(dd + 1) * (DD / 4)];
        float4 w2 = wp[(dd + 2) * (DD / 4)];
        float4 w3 = wp[(dd + 3) * (DD / 4)];
        #pragma unroll
        for (int r = 0; r < R; r++) {
            float4 s4 = *(const float4*)(sb + r * DD + dd);  // broadcast LDS
            acc[r].x = fmaf(s4.x, w0.x, fmaf(s4.y, w1.x, fmaf(s4.z, w2.x, fmaf(s4.w, w3.x, acc[r].x))));
            acc[r].y = fmaf(s4.x, w0.y, fmaf(s4.y, w1.y, fmaf(s4.z, w2.y, fmaf(s4.w, w3.y, acc[r].y))));
            acc[r].z = fmaf(s4.x, w0.z, fmaf(s4.y, w1.z, fmaf(s4.z, w2.z, fmaf(s4.w, w3.z, acc[r].z))));
            acc[r].w = fmaf(s4.x, w0.w, fmaf(s4.y, w1.w, fmaf(s4.z, w2.w, fmaf(s4.w, w3.w, acc[r].w))));
        }
    }

    // store partials, reduce across the 8 d-chunks
    #pragma unroll
    for (int r = 0; r < R; r++)
        sm_red[(dq * R + r) * 32 + col4] = acc[r];
    __syncthreads();

    const float* bias = ga.bias[z];
    float* outp = ga.out[z];
    for (int o = tid; o < R * 32; o += 256) {
        int row = o >> 5, c4 = o & 31;
        float4 sum = sm_red[(0 * R + row) * 32 + c4];
        #pragma unroll
        for (int q = 1; q < 8; q++) {
            float4 v = sm_red[(q * R + row) * 32 + c4];
            sum.x += v.x; sum.y += v.y; sum.z += v.z; sum.w += v.w;
        }
        int col = cc * 128 + c4 * 4;
        float4 bb = *(const float4*)(bias + col);
        sum.x += bb.x; sum.y += bb.y; sum.z += bb.z; sum.w += bb.w;
        if (RES) {
            float4 yv = *(const float4*)(sm_src + row * DD + col);
            sum.x += yv.x; sum.y += yv.y; sum.z += yv.z; sum.w += yv.w;
        }
        *(float4*)(outp + (size_t)(t * R + row) * DD + col) = sum;
    }
}

// ---- block reductions over 512 threads (16 warps) ----
__device__ __forceinline__ float blockReduceSum(float v, float* red) {
    int tid = threadIdx.x, lane = tid & 31, wid = tid >> 5;
    #pragma unroll
    for (int o = 16; o > 0; o >>= 1) v += __shfl_down_sync(0xffffffffu, v, o);
    if (lane == 0) red[wid] = v;
    __syncthreads();
    if (wid == 0) {
        float x = (lane < 16) ? red[lane] : 0.0f;
        #pragma unroll
        for (int o = 8; o > 0; o >>= 1) x += __shfl_down_sync(0xffffffffu, x, o);
        if (lane == 0) red[0] = x;
    }
    __syncthreads();
    float r = red[0];
    __syncthreads();
    return r;
}

__device__ __forceinline__ float blockReduceMax(float v, float* red) {
    int tid = threadIdx.x, lane = tid & 31, wid = tid >> 5;
    #pragma unroll
    for (int o = 16; o > 0; o >>= 1) v = fmaxf(v, __shfl_down_sync(0xffffffffu, v, o));
    if (lane == 0) red[wid] = v;
    __syncthreads();
    if (wid == 0) {
        float x = (lane < 16) ? red[lane] : -3.4e38f;
        #pragma unroll
        for (int o = 8; o > 0; o >>= 1) x = fmaxf(x, __shfl_down_sync(0xffffffffu, x, o));
        if (lane == 0) red[0] = x;
    }
    __syncthreads();
    float r = red[0];
    __syncthreads();
    return r;
}

__device__ __forceinline__ float blockReduceMin(float v, float* red) {
    int tid = threadIdx.x, lane = tid & 31, wid = tid >> 5;
    #pragma unroll
    for (int o = 16; o > 0; o >>= 1) v = fminf(v, __shfl_down_sync(0xffffffffu, v, o));
    if (lane == 0) red[wid] = v;
    __syncthreads();
    if (wid == 0) {
        float x = (lane < 16) ? red[lane] : 3.4e38f;
        #pragma unroll
        for (int o = 8; o > 0; o >>= 1) x = fminf(x, __shfl_down_sync(0xffffffffu, x, o));
        if (lane == 0) red[0] = x;
    }
    __syncthreads();
    float r = red[0];
    __syncthreads();
    return r;
}

// ---- main fused kernel: one block per (batch, channel) ----
__global__ void __launch_bounds__(512)
k_main(Ptr3 x, Ptr3 h, Ptr3 kq,
       const float* __restrict__ kn_g, const float* __restrict__ kn_b,
       const float* __restrict__ norm_g, const float* __restrict__ norm_b)
{
    __shared__ float s_s[DD], s_u2[DD], s_m2[DD], s_coef[DD];
    __shared__ float red[32];

    int b = blockIdx.x, c = blockIdx.y, tid = threadIdx.x;
    int row = c * BB + b;

    float wk = g_wk[(size_t)row * DD + tid];
    float wq = g_wq[(size_t)row * DD + tid];
    float kv = h.p[c][(size_t)b * DD + tid];
    float qv = kq.p[c][(size_t)b * DD + tid];
    float vv = x.p[c][(size_t)b * DD + tid];

    const float inv_d = 1.0f / (float)DD;
    float mu_wk  = blockReduceSum(wk, red) * inv_d;
    float dk     = wk - mu_wk;
    float var_wk = blockReduceSum(dk * dk, red) * inv_d;
    float mu_wq  = blockReduceSum(wq, red) * inv_d;
    float dq     = wq - mu_wq;
    float var_wq = blockReduceSum(dq * dq, red) * inv_d;

    float g  = kn_g[tid];
    float cb = kn_b[tid];

    // rank-1 LN factorization
    float si = kv * rsqrtf(kv * kv * var_wk + EPSF);
    float ti = qv * rsqrtf(qv * qv * var_wq + EPSF);
    float Ai = dk * g;
    float Bi = dq * g;

    float P    = blockReduceSum(Ai * ti, red);
    float Qs   = blockReduceSum(Ai, red);
    float smax = blockReduceMax(si, red);
    float smin = blockReduceMin(si, red);

    // scores[i,j] = s_i * u_j + (j-only terms that cancel in softmax over i)
    float u2 = (P * Bi + Qs * cb) * LOG2E_F;          // log2-space
    float m2 = fmaxf(u2 * smax, u2 * smin);           // max_i of s_i*u_j (log2)
    s_s[tid]  = si;
    s_u2[tid] = u2;
    s_m2[tid] = m2;
    __syncthreads();

    // Pass A: Z_j = sum_i exp2(s_i*u2_j - m2_j)   (thread = column j)
    float z = 0.0f;
    #pragma unroll 8
    for (int i = 0; i < DD; i++)
        z += ex2f(fmaf(s_s[i], u2, -m2));
    s_coef[tid] = vv / z;
    __syncthreads();

    // Pass B: mha_i = sum_j coef_j * exp2(s_i*u2_j - m2_j)   (thread = row i)
    float acc = 0.0f;
    #pragma unroll 8
    for (int j = 0; j < DD; j++)
        acc += s_coef[j] * ex2f(fmaf(si, s_u2[j], -s_m2[j]));

    // residual + LayerNorm
    float y     = acc + vv;
    float mu_y  = blockReduceSum(y, red) * inv_d;
    float dy    = y - mu_y;
    float var_y = blockReduceSum(dy * dy, red) * inv_d;
    float yn    = dy * rsqrtf(var_y + EPSF) * norm_g[tid] + norm_b[tid];

    g_y[(size_t)row * DD + tid] = yn;
}

extern "C" void kernel_launch(void* const* d_in, const int* in_sizes, int n_in,
                              void* d_out, int out_size)
{
    (void)in_sizes; (void)n_in; (void)out_size;
    const float* r    = (const float*)d_in[0];
    const float* g    = (const float*)d_in[1];
    const float* b    = (const float*)d_in[2];
    const float* h_r  = (const float*)d_in[3];
    const float* h_g  = (const float*)d_in[4];
    const float* h_b  = (const float*)d_in[5];
    const float* k_r  = (const float*)d_in[6];
    const float* k_g  = (const float*)d_in[7];
    const float* k_b  = (const float*)d_in[8];
    const float* Wk   = (const float*)d_in[9];
    const float* bk   = (const float*)d_in[10];
    const float* Wq   = (const float*)d_in[11];
    const float* bq   = (const float*)d_in[12];
    const float* kn_g = (const float*)d_in[13];
    const float* kn_b = (const float*)d_in[14];
    const float* norm_g = (const float*)d_in[15];
    const float* norm_b = (const float*)d_in[16];
    const float* fc_w = (const float*)d_in[17];
    const float* fc_b = (const float*)d_in[18];
    float* out = (float*)d_out;

    Ptr3 X  = {{ r,   g,   b   }};
    Ptr3 H  = {{ h_r, h_g, h_b }};
    Ptr3 KQ = {{ k_r, k_g, k_b }};

    // device addresses of symbols + one-time smem opt-in
    static float* wk_dev = nullptr;
    static float* wq_dev = nullptr;
    static float* y_dev  = nullptr;
    if (y_dev == nullptr) {
        void* p = nullptr;
        cudaGetSymbolAddress(&p, g_y);  y_dev  = (float*)p;
        cudaGetSymbolAddress(&p, g_wk); wk_dev = (float*)p;
        cudaGetSymbolAddress(&p, g_wq); wq_dev = (float*)p;
        cudaFuncSetAttribute(k_gemm2<16, false>,
                             cudaFuncAttributeMaxDynamicSharedMemorySize,
                             16 * DD * 4 + 8 * 16 * 32 * 16);
        cudaFuncSetAttribute(k_gemm2<8, true>,
                             cudaFuncAttributeMaxDynamicSharedMemorySize,
                             8 * DD * 4 + 8 * 8 * 32 * 16);
    }

    // Stage 0: transpose Wk, Wq, fc_w into g_wt
    k_transpose<<<dim3(16, 16, 3), dim3(32, 8)>>>(Wk, Wq, fc_w);

    // Stage 1: w_k = h @ Wk.T + bk ; w_q = kidx @ Wq.T + bq  (one launch, z = matrix)
    {
        GemmArgs ga;
        ga.src[0] = H;  ga.src[1] = KQ;
        ga.bias[0] = bk; ga.bias[1] = bq;
        ga.out[0] = wk_dev; ga.out[1] = wq_dev;
        ga.wtsel[0] = 0; ga.wtsel[1] = 1;
        size_t smem = 16 * DD * 4 + 8 * 16 * 32 * 16;  // 32KB src + 64KB red
        k_gemm2<16, false><<<dim3(3 * BB / 16, 4, 2), 256, smem>>>(ga);
    }

    // Stage 2: collapsed attention + residual + LN -> g_y
    k_main<<<dim3(BB, 3), 512>>>(X, H, KQ, kn_g, kn_b, norm_g, norm_b);

    // Stage 3: out = y @ fc_w.T + fc_b + y
    {
        Ptr3 Y = {{ y_dev, y_dev + BB * DD, y_dev + 2 * BB * DD }};
        GemmArgs ga;
        ga.src[0] = Y;  ga.src[1] = Y;
        ga.bias[0] = fc_b; ga.bias[1] = fc_b;
        ga.out[0] = out; ga.out[1] = out;
        ga.wtsel[0] = 2; ga.wtsel[1] = 2;
        size_t smem = 8 * DD * 4 + 8 * 8 * 32 * 16;    // 16KB src + 32KB red
        k_gemm2<8, true><<<dim3(3 * BB / 8, 4, 1), 256, smem>>>(ga);
    }
}

// round 3
// speedup vs baseline: 2.8262x; 1.4119x over previous
#include <cuda_runtime.h>

#define DD 512
#define BB 128
#define EPSF 1e-5f
#define LOG2E_F 1.4426950408889634f
#define TJ 32                    // j-tile width in k_main

// scratch (static device memory — no allocations)
__device__ float g_wk[3 * BB * DD];
__device__ float g_wq[3 * BB * DD];
__device__ float g_y [3 * BB * DD];
__device__ float g_wt[3 * DD * DD];   // transposed Wk, Wq, fc_w

struct Ptr3 { const float* p[3]; };

__device__ __forceinline__ float ex2f(float x) {
    float y;
    asm("ex2.approx.ftz.f32 %0, %1;" : "=f"(y) : "f"(x));
    return y;
}

// ===================== transpose: g_wt[z][d][m] = W_z[m][d] =====================
__global__ void __launch_bounds__(256)
k_transpose(const float* __restrict__ W0, const float* __restrict__ W1,
            const float* __restrict__ W2)
{
    __shared__ float t[32][33];
    const float* W = (blockIdx.z == 0) ? W0 : (blockIdx.z == 1) ? W1 : W2;
    float* O = g_wt + (size_t)blockIdx.z * DD * DD;
    int x  = blockIdx.x * 32 + threadIdx.x;
    int y0 = blockIdx.y * 32;
    #pragma unroll
    for (int i = threadIdx.y; i < 32; i += 8)
        t[i][threadIdx.x] = W[(size_t)(y0 + i) * DD + x];
    __syncthreads();
    int xo  = blockIdx.y * 32 + threadIdx.x;
    int yo0 = blockIdx.x * 32;
    #pragma unroll
    for (int i = threadIdx.y; i < 32; i += 8)
        O[(size_t)(yo0 + i) * DD + xo] = t[threadIdx.x][i];
}

// ===================== GEMM, high-parallelism version =====================
// out[row, m] = sum_d src[row, d] * Wt[d, m] + bias[m] (+ residual src)
// block = 128 threads; tile = 4 rows x 64 cols; in-block K-split 8 (dq = tid>>4).
// grid: (96 row-tiles, 8 col-tiles, Z)
struct GemmArgs {
    Ptr3 src[2];
    const float* bias[2];
    float* out[2];
    int wtsel[2];
};

template <bool RES>
__global__ void __launch_bounds__(128)
k_gemm3(GemmArgs ga)
{
    __shared__ __align__(16) float  sm_src[4 * DD];       // 8 KB
    __shared__ __align__(16) float4 sm_red[8][4][16];     // 8 KB

    int z  = blockIdx.z;
    int rt = blockIdx.x;
    int cc = blockIdx.y;
    int tid = threadIdx.x;

    int c  = (rt * 4) / BB;
    int b0 = (rt * 4) % BB;
    const float* s  = ga.src[z].p[c] + (size_t)b0 * DD;
    const float* Wt = g_wt + (size_t)ga.wtsel[z] * DD * DD + cc * 64;

    #pragma unroll
    for (int i = tid; i < 4 * DD / 4; i += 128)
        ((float4*)sm_src)[i] = ((const float4*)s)[i];
    __syncthreads();

    int c4 = tid & 15;     // 16 col-quads -> 64 cols
    int dq = tid >> 4;     // 8 d-chunks of 64
    const float* wbase = Wt + (size_t)dq * 64 * DD + c4 * 4;
    const float* sb    = sm_src + dq * 64;

    float4 acc[4];
    #pragma unroll
    for (int r = 0; r < 4; r++) acc[r] = make_float4(0.f, 0.f, 0.f, 0.f);

    #pragma unroll 4
    for (int dd = 0; dd < 64; dd += 4) {
        float4 w0 = *(const float4*)(wbase + (size_t)(dd + 0) * DD);
        float4 w1 = *(const float4*)(wbase + (size_t)(dd + 1) * DD);
        float4 w2 = *(const float4*)(wbase + (size_t)(dd + 2) * DD);
        float4 w3 = *(const float4*)(wbase + (size_t)(dd + 3) * DD);
        #pragma unroll
        for (int r = 0; r < 4; r++) {
            float4 s4 = *(const float4*)(sb + r * DD + dd);
            acc[r].x = fmaf(s4.x, w0.x, fmaf(s4.y, w1.x, fmaf(s4.z, w2.x, fmaf(s4.w, w3.x, acc[r].x))));
            acc[r].y = fmaf(s4.x, w0.y, fmaf(s4.y, w1.y, fmaf(s4.z, w2.y, fmaf(s4.w, w3.y, acc[r].y))));
            acc[r].z = fmaf(s4.x, w0.z, fmaf(s4.y, w1.z, fmaf(s4.z, w2.z, fmaf(s4.w, w3.z, acc[r].z))));
            acc[r].w = fmaf(s4.x, w0.w, fmaf(s4.y, w1.w, fmaf(s4.z, w2.w, fmaf(s4.w, w3.w, acc[r].w))));
        }
    }

    #pragma unroll
    for (int r = 0; r < 4; r++)
        sm_red[dq][r][c4] = acc[r];
    __syncthreads();

    if (tid < 64) {
        int r  = tid >> 4;
        int cq = tid & 15;
        float4 sum = sm_red[0][r][cq];
        #pragma unroll
        for (int q = 1; q < 8; q++) {
            float4 v = sm_red[q][r][cq];
            sum.x += v.x; sum.y += v.y; sum.z += v.z; sum.w += v.w;
        }
        int col = cc * 64 + cq * 4;
        float4 bb = *(const float4*)(ga.bias[z] + col);
        sum.x += bb.x; sum.y += bb.y; sum.z += bb.z; sum.w += bb.w;
        if (RES) {
            float4 yv = *(const float4*)(sm_src + r * DD + col);
            sum.x += yv.x; sum.y += yv.y; sum.z += yv.z; sum.w += yv.w;
        }
        *(float4*)(ga.out[z] + (size_t)(rt * 4 + r) * DD + col) = sum;
    }
}

// ---- block reductions over 512 threads (16 warps) ----
__device__ __forceinline__ float blockReduceSum(float v, float* red) {
    int tid = threadIdx.x, lane = tid & 31, wid = tid >> 5;
    #pragma unroll
    for (int o = 16; o > 0; o >>= 1) v += __shfl_down_sync(0xffffffffu, v, o);
    if (lane == 0) red[wid] = v;
    __syncthreads();
    if (wid == 0) {
        float x = (lane < 16) ? red[lane] : 0.0f;
        #pragma unroll
        for (int o = 8; o > 0; o >>= 1) x += __shfl_down_sync(0xffffffffu, x, o);
        if (lane == 0) red[0] = x;
    }
    __syncthreads();
    float r = red[0];
    __syncthreads();
    return r;
}

__device__ __forceinline__ float blockReduceMax(float v, float* red) {
    int tid = threadIdx.x, lane = tid & 31, wid = tid >> 5;
    #pragma unroll
    for (int o = 16; o > 0; o >>= 1) v = fmaxf(v, __shfl_down_sync(0xffffffffu, v, o));
    if (lane == 0) red[wid] = v;
    __syncthreads();
    if (wid == 0) {
        float x = (lane < 16) ? red[lane] : -3.4e38f;
        #pragma unroll
        for (int o = 8; o > 0; o >>= 1) x = fmaxf(x, __shfl_down_sync(0xffffffffu, x, o));
        if (lane == 0) red[0] = x;
    }
    __syncthreads();
    float r = red[0];
    __syncthreads();
    return r;
}

__device__ __forceinline__ float blockReduceMin(float v, float* red) {
    int tid = threadIdx.x, lane = tid & 31, wid = tid >> 5;
    #pragma unroll
    for (int o = 16; o > 0; o >>= 1) v = fminf(v, __shfl_down_sync(0xffffffffu, v, o));
    if (lane == 0) red[wid] = v;
    __syncthreads();
    if (wid == 0) {
        float x = (lane < 16) ? red[lane] : 3.4e38f;
        #pragma unroll
        for (int o = 8; o > 0; o >>= 1) x = fminf(x, __shfl_down_sync(0xffffffffu, x, o));
        if (lane == 0) red[0] = x;
    }
    __syncthreads();
    float r = red[0];
    __syncthreads();
    return r;
}

// ---- main fused kernel: one block per (batch, channel) ----
// Single-pass tiled softmax: per j-tile of TJ columns, compute the exp tile E ONCE,
// reduce column sums -> coef, then accumulate mha. Halves MUFU ex2 count vs 2-pass.
__global__ void __launch_bounds__(512)
k_main(Ptr3 x, Ptr3 h, Ptr3 kq,
       const float* __restrict__ kn_g, const float* __restrict__ kn_b,
       const float* __restrict__ norm_g, const float* __restrict__ norm_b)
{
    extern __shared__ float E[];              // [512][TJ+1], stride 33 (odd -> conflict-free)
    __shared__ float s_s[DD], s_u2[DD], s_v[DD];
    __shared__ float Zpart[16][TJ + 1];
    __shared__ float coefT[TJ];
    __shared__ float red[32];

    const int ESTR = TJ + 1;

    int b = blockIdx.x, c = blockIdx.y, tid = threadIdx.x;
    int row = c * BB + b;

    float wk = g_wk[(size_t)row * DD + tid];
    float wq = g_wq[(size_t)row * DD + tid];
    float kv = h.p[c][(size_t)b * DD + tid];
    float qv = kq.p[c][(size_t)b * DD + tid];
    float vv = x.p[c][(size_t)b * DD + tid];

    const float inv_d = 1.0f / (float)DD;
    float mu_wk  = blockReduceSum(wk, red) * inv_d;
    float dk     = wk - mu_wk;
    float var_wk = blockReduceSum(dk * dk, red) * inv_d;
    float mu_wq  = blockReduceSum(wq, red) * inv_d;
    float dq     = wq - mu_wq;
    float var_wq = blockReduceSum(dq * dq, red) * inv_d;

    float gg = kn_g[tid];
    float cb = kn_b[tid];

    // rank-1 LN factorization
    float si = kv * rsqrtf(kv * kv * var_wk + EPSF);
    float ti = qv * rsqrtf(qv * qv * var_wq + EPSF);
    float Ai = dk * gg;
    float Bi = dq * gg;

    float P    = blockReduceSum(Ai * ti, red);
    float Qs   = blockReduceSum(Ai, red);
    float smax = blockReduceMax(si, red);
    float smin = blockReduceMin(si, red);

    float u2 = (P * Bi + Qs * cb) * LOG2E_F;          // log2-space, j-only terms cancel
    s_s[tid]  = si;
    s_u2[tid] = u2;
    s_v[tid]  = vv;
    __syncthreads();

    int g = tid >> 5;          // warp id: 16 i-groups of 32
    int j = tid & 31;          // lane:    column within tile

    float acc = 0.0f;

    #pragma unroll 1
    for (int jt = 0; jt < DD; jt += TJ) {
        float u2j = s_u2[jt + j];
        float m2j = fmaxf(u2j * smax, u2j * smin);
        float Zl = 0.0f;

        float* Ecol = E + (size_t)(g * 32) * ESTR + j;
        const float* sbase = s_s + g * 32;
        #pragma unroll
        for (int i4 = 0; i4 < 32; i4 += 4) {
            float4 s4 = *(const float4*)(sbase + i4);    // broadcast LDS
            float e0 = ex2f(fmaf(s4.x, u2j, -m2j));
            float e1 = ex2f(fmaf(s4.y, u2j, -m2j));
            float e2 = ex2f(fmaf(s4.z, u2j, -m2j));
            float e3 = ex2f(fmaf(s4.w, u2j, -m2j));
            Zl += (e0 + e1) + (e2 + e3);
            Ecol[(i4 + 0) * ESTR] = e0;
            Ecol[(i4 + 1) * ESTR] = e1;
            Ecol[(i4 + 2) * ESTR] = e2;
            Ecol[(i4 + 3) * ESTR] = e3;
        }
        Zpart[g][j] = Zl;
        __syncthreads();

        if (tid < TJ) {
            float zt = 0.0f;
            #pragma unroll
            for (int w = 0; w < 16; w++) zt += Zpart[w][tid];
            coefT[tid] = s_v[jt + tid] / zt;
        }
        __syncthreads();

        // accumulate: thread i = tid reads its row of E (stride-1 within row, odd row stride)
        const float* Erow = E + (size_t)tid * ESTR;
        #pragma unroll
        for (int jj = 0; jj < TJ; jj += 4) {
            float c0 = coefT[jj + 0], c1 = coefT[jj + 1];
            float c2 = coefT[jj + 2], c3 = coefT[jj + 3];
            acc = fmaf(c0, Erow[jj + 0], acc);
            acc = fmaf(c1, Erow[jj + 1], acc);
            acc = fmaf(c2, Erow[jj + 2], acc);
            acc = fmaf(c3, Erow[jj + 3], acc);
        }
        __syncthreads();     // E reused next tile
    }

    // residual + LayerNorm
    float y     = acc + vv;
    float mu_y  = blockReduceSum(y, red) * inv_d;
    float dy    = y - mu_y;
    float var_y = blockReduceSum(dy * dy, red) * inv_d;
    float yn    = dy * rsqrtf(var_y + EPSF) * norm_g[tid] + norm_b[tid];

    g_y[(size_t)row * DD + tid] = yn;
}

extern "C" void kernel_launch(void* const* d_in, const int* in_sizes, int n_in,
                              void* d_out, int out_size)
{
    (void)in_sizes; (void)n_in; (void)out_size;
    const float* r    = (const float*)d_in[0];
    const float* g    = (const float*)d_in[1];
    const float* b    = (const float*)d_in[2];
    const float* h_r  = (const float*)d_in[3];
    const float* h_g  = (const float*)d_in[4];
    const float* h_b  = (const float*)d_in[5];
    const float* k_r  = (const float*)d_in[6];
    const float* k_g  = (const float*)d_in[7];
    const float* k_b  = (const float*)d_in[8];
    const float* Wk   = (const float*)d_in[9];
    const float* bk   = (const float*)d_in[10];
    const float* Wq   = (const float*)d_in[11];
    const float* bq   = (const float*)d_in[12];
    const float* kn_g = (const float*)d_in[13];
    const float* kn_b = (const float*)d_in[14];
    const float* norm_g = (const float*)d_in[15];
    const float* norm_b = (const float*)d_in[16];
    const float* fc_w = (const float*)d_in[17];
    const float* fc_b = (const float*)d_in[18];
    float* out = (float*)d_out;

    Ptr3 X  = {{ r,   g,   b   }};
    Ptr3 H  = {{ h_r, h_g, h_b }};
    Ptr3 KQ = {{ k_r, k_g, k_b }};

    const size_t E_BYTES = (size_t)DD * (TJ + 1) * sizeof(float);   // 67.6 KB

    static float* wk_dev = nullptr;
    static float* wq_dev = nullptr;
    static float* y_dev  = nullptr;
    if (y_dev == nullptr) {
        void* p = nullptr;
        cudaGetSymbolAddress(&p, g_y);  y_dev  = (float*)p;
        cudaGetSymbolAddress(&p, g_wk); wk_dev = (float*)p;
        cudaGetSymbolAddress(&p, g_wq); wq_dev = (float*)p;
        cudaFuncSetAttribute(k_main, cudaFuncAttributeMaxDynamicSharedMemorySize,
                             (int)E_BYTES);
    }

    // Stage 0: transpose Wk, Wq, fc_w into g_wt
    k_transpose<<<dim3(16, 16, 3), dim3(32, 8)>>>(Wk, Wq, fc_w);

    // Stage 1: w_k = h @ Wk.T + bk ; w_q = kidx @ Wq.T + bq  (z selects matrix)
    {
        GemmArgs ga;
        ga.src[0] = H;  ga.src[1] = KQ;
        ga.bias[0] = bk; ga.bias[1] = bq;
        ga.out[0] = wk_dev; ga.out[1] = wq_dev;
        ga.wtsel[0] = 0; ga.wtsel[1] = 1;
        k_gemm3<false><<<dim3(3 * BB / 4, 8, 2), 128>>>(ga);
    }

    // Stage 2: collapsed attention + residual + LN -> g_y
    k_main<<<dim3(BB, 3), 512, E_BYTES>>>(X, H, KQ, kn_g, kn_b, norm_g, norm_b);

    // Stage 3: out = y @ fc_w.T + fc_b + y
    {
        Ptr3 Y = {{ y_dev, y_dev + BB * DD, y_dev + 2 * BB * DD }};
        GemmArgs ga;
        ga.src[0] = Y;  ga.src[1] = Y;
        ga.bias[0] = fc_b; ga.bias[1] = fc_b;
        ga.out[0] = out; ga.out[1] = out;
        ga.wtsel[0] = 2; ga.wtsel[1] = 2;
        k_gemm3<true><<<dim3(3 * BB / 4, 8, 1), 128>>>(ga);
    }
}